// round 17
// baseline (speedup 1.0000x reference)
#include <cuda_runtime.h>

// SC-based GEMM, collapsed analytically:
//   out[m,n] = sum_k min(t1[m,k], t2[k,n]) * e1[m,k] * e2[k,n]
// t = floor(norm*256), e = sign * 2^{-s} (extra /256 folded into e2).
// Valid because rngSeq = arange(L) and the reference's ascending sequence
// are sorted unary prefixes, so popcount(b1 & b2) == min(t1, t2).
//
// R15 structure (best wall): SINGLE kernel, warp-split-K, full K resident,
// 128 CTAs x 512 threads (one wave), 32x16 tile, 4x4/thread, f32x2 math.
// New: software-pipelined mainloop (even/odd operand buffers) and
// pre-duplicated A-scale pairs in smem (no per-k dup movs).

#define MKN 256
#define TM 32            // tile rows (m)
#define TN 16            // tile cols (n)
#define NW 16            // warps per CTA
#define KW 16            // k per warp (256 / NW)

// dynamic smem (floats):
//   sAt  [256][32] @ 0       (8192 f)
//   sAe2 [256][64] @ 8192    (16384 f, each e duplicated {e,e})
//   sBt  [256][16] @ 24576   (4096 f)
//   sBe  [256][16] @ 28672   (4096 f)
#define OFF_AE 8192
#define OFF_BT 24576
#define OFF_BE 28672
#define SMEM_FLOATS 32768    // 128KB

typedef unsigned long long u64;

__device__ __forceinline__ float2 sc_encode(float x, int extra_shift) {
    int xb   = __float_as_int(x);
    int bits = xb & 0x7FFFFFFF;               // |x| bits
    int q    = (bits >> 23) - 126;            // frexp exponent (normals)
    int s    = ((bits & 0x7FFFFF) == 0) ? (1 - q) : (-q);  // floor(-log2|x|)
    s = max(0, min(s, 8));                    // clip to DATA_WIDTH
    // thr = floor(|x| * 2^(s+8)); power-of-2 scale is exact.
    float thr = floorf(__int_as_float(bits) *
                       __int_as_float((127 + s + 8) << 23));
    // e = sign(x) * 2^{-s-extra}: built directly from bits.
    float e = __int_as_float(((127 - s - extra_shift) << 23) |
                             (xb & 0x80000000u));
    return make_float2(thr, e);
}

// acc_pair += min(at, {bt0,bt1}) * {ae,ae} * {be0,be1}   (packed f32x2)
__device__ __forceinline__ void sc_pair(u64& acc, float at, float bt0,
                                        float bt1, u64 aed, u64 bed) {
    asm("{\n\t"
        ".reg .f32 lo, hi;\n\t"
        ".reg .b64 p;\n\t"
        "min.f32 lo, %1, %2;\n\t"
        "min.f32 hi, %1, %3;\n\t"
        "mov.b64 p, {lo, hi};\n\t"
        "mul.rn.f32x2 p, p, %4;\n\t"
        "fma.rn.f32x2 %0, p, %5, %0;\n\t"
        "}"
        : "+l"(acc)
        : "f"(at), "f"(bt0), "f"(bt1), "l"(aed), "l"(bed));
}

struct KOps {                 // one k-iteration's operands
    float4 at;                // a thresholds (4 m)
    ulonglong2 ae01, ae23;    // a scales, duplicated pairs {e,e}
    float4 bt;                // b thresholds (4 n)
    ulonglong2 be;            // b scales as (j0,j1),(j2,j3) pairs
};

__global__ __launch_bounds__(512)
void sc_gemm_kernel(const float* __restrict__ A,
                    const float* __restrict__ B,
                    float* __restrict__ out) {
    extern __shared__ float smem[];
    float* sAt  = smem;                       // [k][m]
    float* sAe2 = smem + OFF_AE;              // [k][2m] duplicated
    float* sBt  = smem + OFF_BT;              // [k][n]
    float* sBe  = smem + OFF_BE;
    float* sPart = smem;                      // tail overlay (16*512 floats)

    const int t    = threadIdx.x;
    const int lane = t & 31;
    const int w    = t >> 5;                  // warp id 0..15
    const int tn   = lane & 3;                // n-group (0..3)
    const int tm   = lane >> 2;               // m-group (0..7)
    const int m0   = blockIdx.y * TM;
    const int n0   = blockIdx.x * TN;

    // ---- Encode A panel [TM x 256] -> sAt[k][m], sAe2[k][2m]={e,e}.
    {
        int m  = t & 31;
        int kb = (t >> 5) * 16;
        const float* src = A + (m0 + m) * MKN + kb;
        #pragma unroll
        for (int v = 0; v < 4; ++v) {
            float4 x = *(const float4*)(src + v * 4);
            float xs[4] = {x.x, x.y, x.z, x.w};
            #pragma unroll
            for (int j = 0; j < 4; ++j) {
                float2 en = sc_encode(xs[j], 0);
                int k = kb + v * 4 + j;
                sAt[k * TM + m] = en.x;
                *(float2*)&sAe2[k * 2 * TM + 2 * m] =
                    make_float2(en.y, en.y);
            }
        }
    }
    // ---- Encode B panel [256 x TN]: coalesced float4 in, float4 STS out.
    {
        #pragma unroll
        for (int j = 0; j < 2; ++j) {
            int i  = t + j * 512;             // 0..1023 float4 slots
            int k  = i >> 2;                  // 0..255
            int n4 = (i & 3) * 4;             // 0,4,8,12
            float4 x = *(const float4*)(B + k * MKN + n0 + n4);
            float2 e0 = sc_encode(x.x, 8);
            float2 e1 = sc_encode(x.y, 8);
            float2 e2 = sc_encode(x.z, 8);
            float2 e3 = sc_encode(x.w, 8);
            *(float4*)&sBt[k * TN + n4] = make_float4(e0.x, e1.x, e2.x, e3.x);
            *(float4*)&sBe[k * TN + n4] = make_float4(e0.y, e1.y, e2.y, e3.y);
        }
    }
    __syncthreads();

    // ---- Mainloop: software-pipelined over this warp's k-chunk of 16.
    u64 acc01[4] = {0ull, 0ull, 0ull, 0ull};
    u64 acc23[4] = {0ull, 0ull, 0ull, 0ull};

    const int kb = w * KW;

    #define LOADK(dst, kidx) do {                                          \
        int _k = (kidx);                                                   \
        (dst).at   = *(const float4*)&sAt[_k * TM + tm * 4];               \
        (dst).ae01 = *(const ulonglong2*)&sAe2[_k * 2 * TM + tm * 8];      \
        (dst).ae23 = *(const ulonglong2*)&sAe2[_k * 2 * TM + tm * 8 + 4];  \
        (dst).bt   = *(const float4*)&sBt[_k * TN + tn * 4];               \
        (dst).be   = *(const ulonglong2*)&sBe[_k * TN + tn * 4];           \
    } while (0)

    #define MATHK(o) do {                                                  \
        const float* _atp = &(o).at.x;                                     \
        u64 _aed[4] = {(o).ae01.x, (o).ae01.y, (o).ae23.x, (o).ae23.y};    \
        _Pragma("unroll")                                                  \
        for (int i = 0; i < 4; ++i) {                                      \
            sc_pair(acc01[i], _atp[i], (o).bt.x, (o).bt.y, _aed[i],        \
                    (o).be.x);                                             \
            sc_pair(acc23[i], _atp[i], (o).bt.z, (o).bt.w, _aed[i],        \
                    (o).be.y);                                             \
        }                                                                  \
    } while (0)

    {
        KOps b0, b1;
        LOADK(b0, kb);
        #pragma unroll
        for (int kk = 0; kk < KW; kk += 2) {
            LOADK(b1, kb + kk + 1);          // prefetch k+1 before math(k)
            MATHK(b0);
            if (kk + 2 < KW) LOADK(b0, kb + kk + 2);
            MATHK(b1);
        }
    }

    // ---- Cross-warp reduction via smem overlay on the A region.
    __syncthreads();                          // all mainloop reads done
    #pragma unroll
    for (int i = 0; i < 4; ++i) {
        float f0, f1, f2, f3;
        asm("mov.b64 {%0, %1}, %2;" : "=f"(f0), "=f"(f1) : "l"(acc01[i]));
        asm("mov.b64 {%0, %1}, %2;" : "=f"(f2), "=f"(f3) : "l"(acc23[i]));
        *(float4*)&sPart[w * 512 + (tm * 4 + i) * TN + tn * 4] =
            make_float4(f0, f1, f2, f3);
    }
    __syncthreads();

    // One output per thread; fixed warp order -> deterministic.
    {
        float s0 = 0.0f, s1 = 0.0f, s2 = 0.0f, s3 = 0.0f;
        #pragma unroll
        for (int r = 0; r < NW; r += 4) {
            s0 += sPart[(r + 0) * 512 + t];
            s1 += sPart[(r + 1) * 512 + t];
            s2 += sPart[(r + 2) * 512 + t];
            s3 += sPart[(r + 3) * 512 + t];
        }
        int mloc = t >> 4;                    // 0..31
        int nloc = t & 15;                    // 0..15
        out[(m0 + mloc) * MKN + n0 + nloc] = (s0 + s1) + (s2 + s3);
    }
}

extern "C" void kernel_launch(void* const* d_in, const int* in_sizes, int n_in,
                              void* d_out, int out_size) {
    const float* A = (const float*)d_in[0];   // tensor_1 [256,256]
    const float* B = (const float*)d_in[1];   // tensor_2 [256,256]
    // d_in[2] = rngSeq (arange(256)); sortedness folded into the math.
    float* out = (float*)d_out;

    static int configured = 0;                // idempotent attr set
    if (!configured) {
        cudaFuncSetAttribute(sc_gemm_kernel,
                             cudaFuncAttributeMaxDynamicSharedMemorySize,
                             SMEM_FLOATS * 4);
        configured = 1;
    }

    dim3 grid(MKN / TN, MKN / TM);            // 16 x 8 = 128 CTAs, one wave
    sc_gemm_kernel<<<grid, 512, SMEM_FLOATS * 4>>>(A, B, out);
}